// round 5
// baseline (speedup 1.0000x reference)
#include <cuda_runtime.h>
#include <cstdint>

typedef unsigned long long ull;

// ---------------- problem constants ----------------
#define B_   4
#define F_   9
#define MP_  100
#define P_   12000
#define C_   64
#define NY_  400
#define NX_  400
#define NXO_ 4          // NX / POOL_W
#define NPTS (B_ * P_)  // 48000
#define NOUT (B_ * C_ * NY_ * NXO_) // 409600

// main kernel tiling
#define TPB  256
#define NPB  32          // points per group (one per lane)
#define NGRP (NPTS / NPB) // 1500 groups
#define GRID 304         // 2 blocks/SM on 152 SMs (persistent, ticket-fed)
#define MPT  10          // mp per chunk
#define NCH  (MP_ / MPT) // 10 chunks per group
#define NBUF 3           // pipeline depth
#define XSN  (F_ * MPT * NPB)   // 2880 floats staged per chunk
#define XSNB (XSN * 4)          // bytes per chunk buffer
#define CPOPS (XSN * 4 / 16)    // 720 cp.async 16B ops per chunk
#define CHF   (MPT * P_)        // float stride between chunks in gmem

// ---------------- device scratch (no allocs allowed) ----------------
__device__ ull   g_w1p[F_ * 32];   // packed pairs: [f][q] -> (w1'[2q][f], w1'[2q+1][f])
__device__ ull   g_b1p[32];
__device__ ull   g_w2p[32 * 64];   // [q][c] -> (w2'[2q][c], w2'[2q+1][c])
__device__ ull   g_b2p[32];
__device__ float g_z[C_];
__device__ int   g_tick;           // persistent-block work ticket

// ---------------- f32x2 helpers (Blackwell packed fp32) ----------------
__device__ __forceinline__ ull ffma2(ull a, ull b, ull c) {
    ull d;
    asm("fma.rn.f32x2 %0, %1, %2, %3;" : "=l"(d) : "l"(a), "l"(b), "l"(c));
    return d;
}
__device__ __forceinline__ ull fpack(float x, float y) {
    ull r;
    asm("mov.b64 %0, {%1, %2};" : "=l"(r) : "f"(x), "f"(y));
    return r;
}
__device__ __forceinline__ ull fdup(float x) {
    ull r;
    asm("mov.b64 %0, {%1, %2};" : "=l"(r) : "f"(x), "f"(x));
    return r;
}
__device__ __forceinline__ void funpack(ull v, float& x, float& y) {
    asm("mov.b64 {%0, %1}, %2;" : "=f"(x), "=f"(y) : "l"(v));
}
__device__ __forceinline__ ull fmax2(ull a, ull b) {
    float ax, ay, bx, by;
    funpack(a, ax, ay);
    funpack(b, bx, by);
    return fpack(fmaxf(ax, bx), fmaxf(ay, by));
}
__device__ __forceinline__ uint32_t smem_u32(const void* p) {
    return (uint32_t)__cvta_generic_to_shared(p);
}
__device__ __forceinline__ void cp16(uint32_t dst, const float* src) {
    asm volatile("cp.async.ca.shared.global [%0], [%1], 16;" :: "r"(dst), "l"(src));
}

// ---------------- setup: BN fold + weight packing ----------
__global__ void k_setup(const float* __restrict__ w1, const float* __restrict__ b1,
                        const float* __restrict__ g1, const float* __restrict__ be1,
                        const float* __restrict__ m1, const float* __restrict__ v1,
                        const float* __restrict__ w2, const float* __restrict__ b2,
                        const float* __restrict__ g2, const float* __restrict__ be2,
                        const float* __restrict__ m2, const float* __restrict__ v2) {
    __shared__ float s1[C_], bb1[C_], s2[C_], bb2[C_];
    int t = threadIdx.x;
    if (t == 0) g_tick = GRID;   // blocks own group 0..GRID-1 implicitly
    if (t < C_) {
        float s = g1[t] * rsqrtf(v1[t] + 1e-3f);
        s1[t] = s;
        bb1[t] = b1[t] * s + be1[t] - m1[t] * s;
        float ss = g2[t] * rsqrtf(v2[t] + 1e-3f);
        s2[t] = ss;
        float bz = b2[t] * ss + be2[t] - m2[t] * ss;
        bb2[t] = bz;
        g_z[t] = fmaxf(bz, 0.0f);
    }
    __syncthreads();
    for (int i = t; i < F_ * 32; i += 1024) {
        int f = i / 32, q = i % 32;
        g_w1p[i] = fpack(w1[(2 * q) * F_ + f] * s1[2 * q],
                         w1[(2 * q + 1) * F_ + f] * s1[2 * q + 1]);
    }
    for (int i = t; i < 32 * 64; i += 1024) {
        int q = i / 64, c = i % 64;
        g_w2p[i] = fpack(w2[(2 * q) * C_ + c] * s2[2 * q],
                         w2[(2 * q + 1) * C_ + c] * s2[2 * q + 1]);
    }
    if (t < 32) {
        g_b1p[t] = fpack(bb1[2 * t], bb1[2 * t + 1]);
        g_b2p[t] = fpack(bb2[2 * t], bb2[2 * t + 1]);
    }
}

// init out = relu(b2') everywhere. Every 100-cell pool window contains an
// empty canvas cell (12000 pillars on 160000 cells; P(full window) ~ 1e-112),
// so the empty-cell constant is always a valid atomicMax floor.
__global__ void k_init(float* __restrict__ out) {
    int i = blockIdx.x * blockDim.x + threadIdx.x;   // over NOUT/4 float4 rows
    if (i < NOUT / 4) {
        float zc = g_z[(i / NY_) & (C_ - 1)];
        ((float4*)out)[i] = make_float4(zc, zc, zc, zc);
    }
}

// ---------------- main fused persistent kernel ----------------
// 8 warps; lane = point (32 points/group), warp owns 4 channel-pairs.
// Persistent blocks pull groups from a global ticket; the 3-deep cp.async
// pipeline flows continuously across group boundaries (next group's ticket
// fetched 4 chunks early, its first 2 chunks prefetched under this group's
// tail). One barrier per chunk.
__global__ void __launch_bounds__(TPB, 2) k_main(const float* __restrict__ x,
                                                 const int* __restrict__ coords,
                                                 float* __restrict__ out) {
    __shared__ float xs[NBUF][XSN];
    __shared__ float feat[NPB][65];
    __shared__ int   s_next;

    const int tid  = threadIdx.x;
    const int warp = tid >> 5;
    const int lane = tid & 31;

    // stage-1 weights into registers (uniform within warp)
    ull w1r[4][F_];
    #pragma unroll
    for (int j = 0; j < 4; j++)
        #pragma unroll
        for (int f = 0; f < F_; f++)
            w1r[j][f] = g_w1p[f * 32 + warp * 4 + j];

    // cp.async assignment (fixed per thread): 720 16B ops/chunk, <=3/thread
    // idx -> f = idx/80, mpi = (idx%80)>>3, quad = idx&7
    const uint32_t xs_base = smem_u32(&xs[0][0]);
    int      cp_soff[3];   // element offset within a group-chunk
    uint32_t cp_doff[3];   // byte offset within a buffer
    bool     cp_on[3];
    #pragma unroll
    for (int k = 0; k < 3; k++) {
        int idx = tid + k * TPB;
        cp_on[k] = idx < CPOPS;
        int ii   = cp_on[k] ? idx : 0;
        int f    = ii / (MPT * 8);
        int r    = ii - f * (MPT * 8);
        int mpi  = r >> 3;
        int q    = r & 7;
        cp_soff[k] = f * (MP_ * P_) + mpi * P_ + q * 4;
        cp_doff[k] = (uint32_t)(((f * MPT + mpi) * NPB + q * 4) * 4);
    }

    // group base pointer: x + batch*F*MP*P + (point offset within batch)
    auto gbase = [&](int g) -> const float* {
        int g0 = g * NPB;
        int b  = g0 / P_;                 // groups never straddle batches
        return x + (size_t)b * (F_ * MP_ * P_) + (g0 - b * P_);
    };

    int gid = blockIdx.x;
    const float* base = gbase(gid);

    // prologue: prefetch chunks 0,1 of first group
    #pragma unroll
    for (int k = 0; k < 3; k++)
        if (cp_on[k]) cp16(xs_base + cp_doff[k], base + cp_soff[k]);
    asm volatile("cp.async.commit_group;");
    #pragma unroll
    for (int k = 0; k < 3; k++)
        if (cp_on[k]) cp16(xs_base + XSNB + cp_doff[k], base + cp_soff[k] + CHF);
    asm volatile("cp.async.commit_group;");

    int bufc = 0, bufn = 2;
    ull m[4];
    #pragma unroll
    for (int j = 0; j < 4; j++) m[j] = 0xFF800000FF800000ull;  // (-inf,-inf)

    for (;;) {
        int ngid = 0;
        const float* nbase = base;
        bool have = false;

        #pragma unroll 1
        for (int c = 0; c < NCH; ++c) {
            // wait for chunk c (the newest in-flight group may stay pending)
            if (c == NCH - 1 && !have) asm volatile("cp.async.wait_group 0;");
            else                       asm volatile("cp.async.wait_group 1;");
            __syncthreads();   // chunk c visible; all done reading buf[bufn]

            if (c == 5 && tid == 0) s_next = atomicAdd(&g_tick, 1);
            if (c == 8) {      // 3 barriers after the write -> visible
                ngid = s_next;
                have = ngid < NGRP;
                if (have) nbase = gbase(ngid);
            }

            // prefetch chunk c+2 (next group's chunk 0/1 when c>=8)
            if (c < NCH - 2) {
                uint32_t d = xs_base + (uint32_t)bufn * XSNB;
                const float* s = base + c * CHF;   // chunk c+2 = base+(c+2)*CHF
                #pragma unroll
                for (int k = 0; k < 3; k++)
                    if (cp_on[k]) cp16(d + cp_doff[k], s + 2 * CHF + cp_soff[k]);
                asm volatile("cp.async.commit_group;");
            } else if (have) {
                uint32_t d = xs_base + (uint32_t)bufn * XSNB;
                const float* s = nbase + (c - (NCH - 2)) * CHF;
                #pragma unroll
                for (int k = 0; k < 3; k++)
                    if (cp_on[k]) cp16(d + cp_doff[k], s + cp_soff[k]);
                asm volatile("cp.async.commit_group;");
            }

            const float* xc = &xs[bufc][0];
            #pragma unroll
            for (int mpi = 0; mpi < MPT; ++mpi) {
                ull xd0 = fdup(xc[(0 * MPT + mpi) * NPB + lane]);
                ull a0 = ffma2(xd0, w1r[0][0], 0ull);
                ull a1 = ffma2(xd0, w1r[1][0], 0ull);
                ull a2 = ffma2(xd0, w1r[2][0], 0ull);
                ull a3 = ffma2(xd0, w1r[3][0], 0ull);
                #pragma unroll
                for (int f = 1; f < F_; f++) {
                    ull xd = fdup(xc[(f * MPT + mpi) * NPB + lane]);
                    a0 = ffma2(xd, w1r[0][f], a0);
                    a1 = ffma2(xd, w1r[1][f], a1);
                    a2 = ffma2(xd, w1r[2][f], a2);
                    a3 = ffma2(xd, w1r[3][f], a3);
                }
                m[0] = fmax2(m[0], a0);
                m[1] = fmax2(m[1], a1);
                m[2] = fmax2(m[2], a2);
                m[3] = fmax2(m[3], a3);
            }
            bufc = (bufc == NBUF - 1) ? 0 : bufc + 1;
            bufn = (bufn == NBUF - 1) ? 0 : bufn + 1;
        }

        // ---- epilogue for group gid ----
        // bias + ReLU after the max (exact: max_mp(Wx+b) = max_mp(Wx)+b)
        #pragma unroll
        for (int j = 0; j < 4; j++) {
            float lo, hi, bl, bh;
            funpack(m[j], lo, hi);
            funpack(g_b1p[warp * 4 + j], bl, bh);
            int c0 = (warp * 4 + j) * 2;
            feat[lane][c0]     = fmaxf(lo + bl, 0.0f);
            feat[lane][c0 + 1] = fmaxf(hi + bh, 0.0f);
            m[j] = 0xFF800000FF800000ull;   // reset for next group
        }
        __syncthreads();

        // stage 2: 64->64 affine; w2 pairs from global (L2-resident, 16KB)
        const ull* __restrict__ w2g = g_w2p + warp * 4 * 64;
        ull acc[4];
        #pragma unroll
        for (int j = 0; j < 4; j++) acc[j] = g_b2p[warp * 4 + j];
        #pragma unroll 8
        for (int c = 0; c < C_; c++) {
            ull fd = fdup(feat[lane][c]);
            #pragma unroll
            for (int j = 0; j < 4; j++)
                acc[j] = ffma2(fd, w2g[j * 64 + c], acc[j]);
        }

        // scatter-max into pooled output; signed-int max == float max for the
        // >=0 floor, and negative bit patterns lose to >=0 => free ReLU.
        const int  g  = gid * NPB + lane;
        const int4 c4 = ((const int4*)coords)[g];   // x=batch, z=y, w=x
        const int  xo = c4.w / 100;
        int* oi = (int*)out;
        #pragma unroll
        for (int j = 0; j < 4; j++) {
            float lo, hi;
            funpack(acc[j], lo, hi);
            int c0 = (warp * 4 + j) * 2;
            atomicMax(&oi[((c4.x * C_ + c0) * NY_ + c4.z) * NXO_ + xo], __float_as_int(lo));
            atomicMax(&oi[((c4.x * C_ + c0 + 1) * NY_ + c4.z) * NXO_ + xo], __float_as_int(hi));
        }

        if (!have) break;
        gid  = ngid;
        base = nbase;
    }
}

// ---------------- launch ----------------
extern "C" void kernel_launch(void* const* d_in, const int* in_sizes, int n_in,
                              void* d_out, int out_size) {
    const float* x      = (const float*)d_in[0];
    const int*   coords = (const int*)d_in[1];
    const float* w1  = (const float*)d_in[2];
    const float* b1  = (const float*)d_in[3];
    const float* g1  = (const float*)d_in[4];
    const float* be1 = (const float*)d_in[5];
    const float* m1  = (const float*)d_in[6];
    const float* v1  = (const float*)d_in[7];
    const float* w2  = (const float*)d_in[8];
    const float* b2  = (const float*)d_in[9];
    const float* g2  = (const float*)d_in[10];
    const float* be2 = (const float*)d_in[11];
    const float* m2  = (const float*)d_in[12];
    const float* v2  = (const float*)d_in[13];
    float* out = (float*)d_out;

    k_setup<<<1, 1024>>>(w1, b1, g1, be1, m1, v1, w2, b2, g2, be2, m2, v2);
    k_init<<<(NOUT / 4 + 511) / 512, 512>>>(out);
    k_main<<<GRID, TPB>>>(x, coords, out);
}